// round 7
// baseline (speedup 1.0000x reference)
#include <cuda_runtime.h>
#include <cuda_bf16.h>
#include <cstdint>

#define NN 8192
#define IN_F 128
#define OUT_F 64
#define ALPHA 0.2f

#define TI 128                 // CTA row tile
#define BK 128                 // j per B stage
#define SPLITS 8
#define JSPAN (NN / SPLITS)    // 1024
#define NTI (NN / TI)          // 64

#define ROWB 576               // bytes per n-row in fragment-packed B stage (512 data + 64 pad)

// Scratch
__device__ float g_s1[NN];
__device__ float g_s2[NN];
__device__ __nv_bfloat16 g_WhT_hi[OUT_F * NN];   // transposed Wh, bf16 hi
__device__ __nv_bfloat16 g_WhT_lo[OUT_F * NN];   // bf16 residual
__device__ float g_accP[SPLITS][NN][OUT_F];
__device__ float g_lP[SPLITS][NN];

// pack two fp32 -> {low16=bf16(x0), high16=bf16(x1)} by truncation
__device__ __forceinline__ uint32_t pack_bf16(float x0, float x1) {
    return __byte_perm(__float_as_uint(x0), __float_as_uint(x1), 0x7632);
}
__device__ __forceinline__ float bf16_trunc_f(float x) {
    return __uint_as_float(__float_as_uint(x) & 0xFFFF0000u);
}

__device__ __forceinline__ void mma16816(float* d,
                                         uint32_t a0, uint32_t a1, uint32_t a2, uint32_t a3,
                                         uint32_t b0, uint32_t b1) {
    asm volatile(
        "mma.sync.aligned.m16n8k16.row.col.f32.bf16.bf16.f32 "
        "{%0,%1,%2,%3}, {%4,%5,%6,%7}, {%8,%9}, {%0,%1,%2,%3};"
        : "+f"(d[0]), "+f"(d[1]), "+f"(d[2]), "+f"(d[3])
        : "r"(a0), "r"(a1), "r"(a2), "r"(a3), "r"(b0), "r"(b1));
}

// ---------------------------------------------------------------------------
// Kernel 1: Wh = h@W; s1/s2; WhT hi/lo bf16 split.  128 CTAs x 64 rows.
// ---------------------------------------------------------------------------
__global__ __launch_bounds__(256) void wh_kernel(const float* __restrict__ h,
                                                 const float* __restrict__ W,
                                                 const float* __restrict__ a) {
    __shared__ __align__(16) float hT[IN_F][68];   // [k][row], xor-swizzled rows
    __shared__ float a_s[2 * OUT_F];

    const int t = threadIdx.x;
    const int blockRow = blockIdx.x * 64;

    // load h tile transposed (swizzle row by ((k>>2)&15)<<2 to spread STS banks)
#pragma unroll
    for (int it = 0; it < 8; ++it) {
        int idx = it * 256 + t;
        int row = idx >> 5;            // 0..63
        int k4 = idx & 31;             // float4 index along k
        float4 v = *(const float4*)&h[(size_t)(blockRow + row) * IN_F + k4 * 4];
#pragma unroll
        for (int c = 0; c < 4; ++c) {
            int k = k4 * 4 + c;
            int rsw = row ^ (((k >> 2) & 15) << 2);
            hT[k][rsw] = ((const float*)&v)[c];
        }
    }
    if (t < 2 * OUT_F) a_s[t] = a[t];
    __syncthreads();

    const int r0 = (t >> 4) * 4;
    const int c0 = (t & 15) * 4;

    float acc[4][4];
#pragma unroll
    for (int i = 0; i < 4; ++i)
#pragma unroll
        for (int j = 0; j < 4; ++j) acc[i][j] = 0.f;

    const float4* Wv = (const float4*)W;
#pragma unroll 4
    for (int k = 0; k < IN_F; ++k) {
        int rsw = r0 ^ (((k >> 2) & 15) << 2);
        float4 hv = *(const float4*)&hT[k][rsw];
        float4 wv = __ldg(&Wv[k * 16 + (c0 >> 2)]);
        const float* hp = (const float*)&hv;
        const float* wp = (const float*)&wv;
#pragma unroll
        for (int i = 0; i < 4; ++i)
#pragma unroll
            for (int j = 0; j < 4; ++j) acc[i][j] += hp[i] * wp[j];
    }

    // s1/s2 partial dots + reduce over the 16 col-threads (lane bits 0..3)
    {
        float p1[4], p2[4];
#pragma unroll
        for (int i = 0; i < 4; ++i) {
            p1[i] = acc[i][0] * a_s[c0] + acc[i][1] * a_s[c0 + 1] +
                    acc[i][2] * a_s[c0 + 2] + acc[i][3] * a_s[c0 + 3];
            p2[i] = acc[i][0] * a_s[OUT_F + c0] + acc[i][1] * a_s[OUT_F + c0 + 1] +
                    acc[i][2] * a_s[OUT_F + c0 + 2] + acc[i][3] * a_s[OUT_F + c0 + 3];
        }
#pragma unroll
        for (int off = 1; off < 16; off <<= 1) {
#pragma unroll
            for (int i = 0; i < 4; ++i) {
                p1[i] += __shfl_xor_sync(0xffffffffu, p1[i], off);
                p2[i] += __shfl_xor_sync(0xffffffffu, p2[i], off);
            }
        }
        if ((t & 15) == 0) {
#pragma unroll
            for (int i = 0; i < 4; ++i) {
                g_s1[blockRow + r0 + i] = p1[i];
                g_s2[blockRow + r0 + i] = p2[i];
            }
        }
    }

    // transpose via smem (alias hT), then bf16 hi/lo writeout
    __syncthreads();
    float* tr = &hT[0][0];               // tr[col*68 + row], 64x64 fits
#pragma unroll
    for (int i = 0; i < 4; ++i)
#pragma unroll
        for (int j = 0; j < 4; ++j)
            tr[(c0 + j) * 68 + (r0 + i)] = acc[i][j];
    __syncthreads();

    {
        const int f = t >> 2;            // col 0..63
        const int q = t & 3;             // 16-row block
#pragma unroll
        for (int m = 0; m < 4; ++m) {
            float4 v = *(const float4*)&tr[f * 68 + q * 16 + m * 4];
            float hi0 = bf16_trunc_f(v.x), hi1 = bf16_trunc_f(v.y);
            float hi2 = bf16_trunc_f(v.z), hi3 = bf16_trunc_f(v.w);
            size_t o = (size_t)f * NN + blockRow + q * 16 + m * 4;
            *(uint2*)&g_WhT_hi[o] = make_uint2(pack_bf16(hi0, hi1), pack_bf16(hi2, hi3));
            *(uint2*)&g_WhT_lo[o] = make_uint2(pack_bf16(v.x - hi0, v.y - hi1),
                                               pack_bf16(v.z - hi2, v.w - hi3));
        }
    }
}

// ---------------------------------------------------------------------------
// Kernel 2: mma.sync bf16 attention. Fragment-packed B in SMEM (1 LDS.128 per
// nt per chunk), adj prefetch pipeline. grid=(64, 8), 8 warps.
// ---------------------------------------------------------------------------
__global__ void __launch_bounds__(256, 2) attn_kernel(const int* __restrict__ adj) {
    __shared__ __align__(16) unsigned char Bs[64 * ROWB];
    __shared__ __align__(16) float s2_s[JSPAN];

    const int t = threadIdx.x;
    const int wid = t >> 5;
    const int lane = t & 31;
    const int qr = lane >> 2;
    const int qm = lane & 3;

    const int iBase = blockIdx.x * TI;
    const int split = blockIdx.y;
    const int jStart = split * JSPAN;

    const int r0 = wid * 16 + qr;
    const int r1 = r0 + 8;
    const float s1r0 = g_s1[iBase + r0];
    const float s1r1 = g_s1[iBase + r1];
    const int* __restrict__ row0 = adj + (size_t)(iBase + r0) * NN;
    const int* __restrict__ row1 = adj + (size_t)(iBase + r1) * NN;

    {
        const float4* src = (const float4*)&g_s2[jStart];
        ((float4*)s2_s)[t] = src[t];
    }

    float d[8][4];
#pragma unroll
    for (int nt = 0; nt < 8; ++nt)
#pragma unroll
        for (int i = 0; i < 4; ++i) d[nt][i] = 0.f;
    float lsum0 = 0.f, lsum1 = 0.f;

    // adj prefetch registers (chunk pipeline)
    int2 A0n, A1n, A2n, A3n;
    {
        int gj = jStart + 2 * qm;
        A0n = __ldg((const int2*)(row0 + gj));
        A2n = __ldg((const int2*)(row0 + gj + 8));
        A1n = __ldg((const int2*)(row1 + gj));
        A3n = __ldg((const int2*)(row1 + gj + 8));
    }

    const unsigned char* bRow = Bs + qr * ROWB + qm * 16;

    for (int stage = 0; stage < JSPAN / BK; ++stage) {
        const int jStage = jStart + stage * BK;

        __syncthreads();   // prior MMAs' B reads done (also covers s2 on stage 0)

        // ---- stage B: fragment-packed. item (n, c): entry(qm) = {hi kpair(2qm),
        //      hi kpair(2qm+8), lo kpair(2qm), lo kpair(2qm+8)} at n*576+c*64+qm*16
#pragma unroll
        for (int half = 0; half < 2; ++half) {
            int idx = half * 256 + t;
            int n = idx >> 3;             // 0..63
            int c = idx & 7;              // chunk
            const uint4* hsrc = (const uint4*)(g_WhT_hi + (size_t)n * NN + jStage + c * 16);
            const uint4* lsrc = (const uint4*)(g_WhT_lo + (size_t)n * NN + jStage + c * 16);
            uint4 u = hsrc[0], v = hsrc[1];
            uint4 ul = lsrc[0], vl = lsrc[1];
            unsigned char* dst = Bs + n * ROWB + c * 64;
            const uint32_t* up = (const uint32_t*)&u;
            const uint32_t* vp = (const uint32_t*)&v;
            const uint32_t* ulp = (const uint32_t*)&ul;
            const uint32_t* vlp = (const uint32_t*)&vl;
#pragma unroll
            for (int q = 0; q < 4; ++q)
                *(uint4*)(dst + q * 16) = make_uint4(up[q], vp[q], ulp[q], vlp[q]);
        }
        __syncthreads();

#pragma unroll
        for (int c = 0; c < 8; ++c) {
            const int jc = stage * BK + c * 16 + 2 * qm;

            int2 A0 = A0n, A1 = A1n, A2 = A2n, A3 = A3n;
            // prefetch next chunk (last iteration: benign dummy reload)
            {
                int gjn = (c < 7) ? (jStage + (c + 1) * 16 + 2 * qm)
                                  : ((stage < JSPAN / BK - 1) ? (jStage + BK + 2 * qm)
                                                              : (jStart + 2 * qm));
                A0n = __ldg((const int2*)(row0 + gjn));
                A2n = __ldg((const int2*)(row0 + gjn + 8));
                A1n = __ldg((const int2*)(row1 + gjn));
                A3n = __ldg((const int2*)(row1 + gjn + 8));
            }

            float2 s2a = *(const float2*)&s2_s[jc];
            float2 s2b = *(const float2*)&s2_s[jc + 8];

            float e, p00, p01, p02, p03, p10, p11, p12, p13;
            e = s1r0 + s2a.x; e = fmaxf(e, ALPHA * e); p00 = (A0.x > 0) ? __expf(e) : 0.f;
            e = s1r0 + s2a.y; e = fmaxf(e, ALPHA * e); p01 = (A0.y > 0) ? __expf(e) : 0.f;
            e = s1r0 + s2b.x; e = fmaxf(e, ALPHA * e); p02 = (A2.x > 0) ? __expf(e) : 0.f;
            e = s1r0 + s2b.y; e = fmaxf(e, ALPHA * e); p03 = (A2.y > 0) ? __expf(e) : 0.f;
            e = s1r1 + s2a.x; e = fmaxf(e, ALPHA * e); p10 = (A1.x > 0) ? __expf(e) : 0.f;
            e = s1r1 + s2a.y; e = fmaxf(e, ALPHA * e); p11 = (A1.y > 0) ? __expf(e) : 0.f;
            e = s1r1 + s2b.x; e = fmaxf(e, ALPHA * e); p12 = (A3.x > 0) ? __expf(e) : 0.f;
            e = s1r1 + s2b.y; e = fmaxf(e, ALPHA * e); p13 = (A3.y > 0) ? __expf(e) : 0.f;

            lsum0 += (p00 + p01) + (p02 + p03);
            lsum1 += (p10 + p11) + (p12 + p13);

            uint32_t a0h = pack_bf16(p00, p01), a2h = pack_bf16(p02, p03);
            uint32_t a1h = pack_bf16(p10, p11), a3h = pack_bf16(p12, p13);
            uint32_t a0l = pack_bf16(p00 - bf16_trunc_f(p00), p01 - bf16_trunc_f(p01));
            uint32_t a2l = pack_bf16(p02 - bf16_trunc_f(p02), p03 - bf16_trunc_f(p03));
            uint32_t a1l = pack_bf16(p10 - bf16_trunc_f(p10), p11 - bf16_trunc_f(p11));
            uint32_t a3l = pack_bf16(p12 - bf16_trunc_f(p12), p13 - bf16_trunc_f(p13));

            const unsigned char* bp = bRow + c * 64;
#pragma unroll
            for (int nt = 0; nt < 8; ++nt) {
                uint4 b = *(const uint4*)(bp + nt * 8 * ROWB);
                mma16816(d[nt], a0h, a1h, a2h, a3h, b.x, b.y);   // Phi * Whi
                mma16816(d[nt], a0h, a1h, a2h, a3h, b.z, b.w);   // Phi * Wlo
                mma16816(d[nt], a0l, a1l, a2l, a3l, b.x, b.y);   // Plo * Whi
            }
        }
    }

    // row sums across the quad
    lsum0 += __shfl_xor_sync(0xffffffffu, lsum0, 1);
    lsum0 += __shfl_xor_sync(0xffffffffu, lsum0, 2);
    lsum1 += __shfl_xor_sync(0xffffffffu, lsum1, 1);
    lsum1 += __shfl_xor_sync(0xffffffffu, lsum1, 2);
    if (qm == 0) {
        g_lP[split][iBase + r0] = lsum0;
        g_lP[split][iBase + r1] = lsum1;
    }

    // write partials
    {
        float* base0 = &g_accP[split][iBase + r0][0];
        float* base1 = &g_accP[split][iBase + r1][0];
#pragma unroll
        for (int nt = 0; nt < 8; ++nt) {
            int cb = nt * 8 + 2 * qm;
            *(float2*)&base0[cb] = make_float2(d[nt][0], d[nt][1]);
            *(float2*)&base1[cb] = make_float2(d[nt][2], d[nt][3]);
        }
    }
}

// ---------------------------------------------------------------------------
// Kernel 3: sum split partials -> normalize -> ELU.
// ---------------------------------------------------------------------------
__global__ __launch_bounds__(256) void combine_kernel(float* __restrict__ out) {
    __shared__ float linv_s[16];
    const int t = threadIdx.x;
    const int rowBase = blockIdx.x * 16;

    if (t < 16) {
        int row = rowBase + t;
        float L = 0.f;
#pragma unroll
        for (int s = 0; s < SPLITS; ++s) L += g_lP[s][row];
        linv_s[t] = 1.f / L;
    }
    __syncthreads();

    const int rr = t >> 4;
    const int c4 = t & 15;
    const int row = rowBase + rr;

    float4 acc = make_float4(0.f, 0.f, 0.f, 0.f);
#pragma unroll
    for (int s = 0; s < SPLITS; ++s) {
        float4 v = *(const float4*)&g_accP[s][row][c4 * 4];
        acc.x += v.x; acc.y += v.y; acc.z += v.z; acc.w += v.w;
    }
    float li = linv_s[rr];
    float x0 = acc.x * li, x1 = acc.y * li, x2 = acc.z * li, x3 = acc.w * li;
    x0 = (x0 > 0.f) ? x0 : expm1f(x0);
    x1 = (x1 > 0.f) ? x1 : expm1f(x1);
    x2 = (x2 > 0.f) ? x2 : expm1f(x2);
    x3 = (x3 > 0.f) ? x3 : expm1f(x3);
    *(float4*)&out[(size_t)row * OUT_F + c4 * 4] = make_float4(x0, x1, x2, x3);
}

// ---------------------------------------------------------------------------
extern "C" void kernel_launch(void* const* d_in, const int* in_sizes, int n_in,
                              void* d_out, int out_size) {
    const float* h   = (const float*)d_in[0];   // 8192 x 128
    const int*   adj = (const int*)d_in[1];     // 8192 x 8192
    const float* W   = (const float*)d_in[2];   // 128 x 64
    const float* a   = (const float*)d_in[3];   // 128 x 1
    float* out = (float*)d_out;                 // 8192 x 64

    wh_kernel<<<NN / 64, 256>>>(h, W, a);
    attn_kernel<<<dim3(NTI, SPLITS), 256>>>(adj);
    combine_kernel<<<NN / 16, 256>>>(out);
}

// round 8
// speedup vs baseline: 1.1559x; 1.1559x over previous
#include <cuda_runtime.h>
#include <cuda_bf16.h>
#include <cstdint>

#define NN 8192
#define IN_F 128
#define OUT_F 64
#define ALPHA 0.2f

#define TI 128                 // CTA row tile
#define BK 128                 // j per B stage
#define SPLITS 8
#define JSPAN (NN / SPLITS)    // 1024
#define NTI (NN / TI)          // 64

#define BSTRIDE 272            // bytes per n-row in B stage (128*2 + 16 pad) -> conflict-free
#define BHALF 17408            // 64 * 272

// Scratch
__device__ float g_s1[NN];
__device__ float g_s2[NN];
__device__ __nv_bfloat16 g_WhT_hi[OUT_F * NN];   // transposed Wh, bf16 hi
__device__ __nv_bfloat16 g_WhT_lo[OUT_F * NN];   // bf16 residual
__device__ float g_accP[SPLITS][NN][OUT_F];
__device__ float g_lP[SPLITS][NN];

// pack two fp32 -> {low16=bf16(x0), high16=bf16(x1)} by truncation
__device__ __forceinline__ uint32_t pack_bf16(float x0, float x1) {
    return __byte_perm(__float_as_uint(x0), __float_as_uint(x1), 0x7632);
}
__device__ __forceinline__ float bf16_trunc_f(float x) {
    return __uint_as_float(__float_as_uint(x) & 0xFFFF0000u);
}

__device__ __forceinline__ void mma16816(float* d,
                                         uint32_t a0, uint32_t a1, uint32_t a2, uint32_t a3,
                                         uint32_t b0, uint32_t b1) {
    asm volatile(
        "mma.sync.aligned.m16n8k16.row.col.f32.bf16.bf16.f32 "
        "{%0,%1,%2,%3}, {%4,%5,%6,%7}, {%8,%9}, {%0,%1,%2,%3};"
        : "+f"(d[0]), "+f"(d[1]), "+f"(d[2]), "+f"(d[3])
        : "r"(a0), "r"(a1), "r"(a2), "r"(a3), "r"(b0), "r"(b1));
}

// ---------------------------------------------------------------------------
// Kernel 1: Wh = h@W; s1 = Wh@a1; s2 = Wh@a2; WhT hi/lo bf16 split.
// (round-6 version, measured 24.99us)
// ---------------------------------------------------------------------------
__global__ __launch_bounds__(256) void wh_kernel(const float* __restrict__ h,
                                                 const float* __restrict__ W,
                                                 const float* __restrict__ a) {
    __shared__ float W_s[IN_F * OUT_F];
    __shared__ float h_s[4][IN_F];
    __shared__ float a_s[2 * OUT_F];
    __shared__ float red1[8], red2[8];
    __shared__ float tr[OUT_F][17];

    const int t = threadIdx.x;
    const int blockRow = blockIdx.x * 16;

    for (int i = t; i < IN_F * OUT_F; i += 256) W_s[i] = W[i];
    if (t < 2 * OUT_F) a_s[t] = a[t];

    const int g = t >> 6;
    const int c = t & 63;

    for (int rg = 0; rg < 4; ++rg) {
        const int rowBase = blockRow + rg * 4;
        __syncthreads();
        for (int i = t; i < 4 * IN_F; i += 256)
            h_s[i >> 7][i & 127] = h[(size_t)(rowBase + (i >> 7)) * IN_F + (i & 127)];
        __syncthreads();

        float acc = 0.f;
#pragma unroll 8
        for (int k = 0; k < IN_F; ++k)
            acc += h_s[g][k] * W_s[k * OUT_F + c];

        tr[c][rg * 4 + g] = acc;

        float v1 = acc * a_s[c];
        float v2 = acc * a_s[OUT_F + c];
#pragma unroll
        for (int off = 16; off > 0; off >>= 1) {
            v1 += __shfl_down_sync(0xffffffffu, v1, off);
            v2 += __shfl_down_sync(0xffffffffu, v2, off);
        }
        if ((t & 31) == 0) { red1[t >> 5] = v1; red2[t >> 5] = v2; }
        __syncthreads();
        if (t < 4) {
            g_s1[rowBase + t] = red1[2 * t] + red1[2 * t + 1];
            g_s2[rowBase + t] = red2[2 * t] + red2[2 * t + 1];
        }
    }
    __syncthreads();

    // transposed bf16 hi/lo write-out: thread t -> col cc=t>>2, rows q*4..+3
    {
        const int cc = t >> 2;
        const int q = t & 3;
        float v[4], hi[4], lo[4];
#pragma unroll
        for (int i = 0; i < 4; ++i) {
            v[i] = tr[cc][q * 4 + i];
            hi[i] = bf16_trunc_f(v[i]);
            lo[i] = v[i] - hi[i];
        }
        size_t o = (size_t)cc * NN + blockRow + q * 4;
        uint2 ph = make_uint2(pack_bf16(hi[0], hi[1]), pack_bf16(hi[2], hi[3]));
        uint2 pl = make_uint2(pack_bf16(lo[0], lo[1]), pack_bf16(lo[2], lo[3]));
        *(uint2*)&g_WhT_hi[o] = ph;
        *(uint2*)&g_WhT_lo[o] = pl;
    }
}

// ---------------------------------------------------------------------------
// Kernel 2: mma.sync bf16 attention (round-6 body) + adj register
// double-buffer prefetch. grid=(64 i-tiles, 8 splits), 8 warps.
// ---------------------------------------------------------------------------
__global__ void __launch_bounds__(256) attn_kernel(const int* __restrict__ adj) {
    __shared__ __align__(16) unsigned char Bs[2 * BHALF];  // hi | lo, 64 rows x 272B
    __shared__ __align__(16) float s2_s[JSPAN];

    const int t = threadIdx.x;
    const int wid = t >> 5;
    const int lane = t & 31;
    const int qr = lane >> 2;      // 0..7
    const int qm = lane & 3;       // 0..3

    const int iBase = blockIdx.x * TI;
    const int split = blockIdx.y;
    const int jStart = split * JSPAN;

    const int r0 = wid * 16 + qr;      // local row for a0/a2
    const int r1 = r0 + 8;             // a1/a3
    const float s1r0 = g_s1[iBase + r0];
    const float s1r1 = g_s1[iBase + r1];
    const int* __restrict__ row0 = adj + (size_t)(iBase + r0) * NN;
    const int* __restrict__ row1 = adj + (size_t)(iBase + r1) * NN;

    // s2 span -> smem
    {
        const float4* src = (const float4*)&g_s2[jStart];
        ((float4*)s2_s)[t] = src[t];
    }

    float d[8][4];
#pragma unroll
    for (int nt = 0; nt < 8; ++nt)
#pragma unroll
        for (int i = 0; i < 4; ++i) d[nt][i] = 0.f;
    float lsum0 = 0.f, lsum1 = 0.f;

    // adj prefetch registers (chunk pipeline)
    int2 A0n, A1n, A2n, A3n;
    {
        int gj = jStart + 2 * qm;
        A0n = __ldg((const int2*)(row0 + gj));
        A2n = __ldg((const int2*)(row0 + gj + 8));
        A1n = __ldg((const int2*)(row1 + gj));
        A3n = __ldg((const int2*)(row1 + gj + 8));
    }

    for (int stage = 0; stage < JSPAN / BK; ++stage) {
        const int jStage = jStart + stage * BK;

        __syncthreads();   // prior MMAs done before overwriting Bs (also covers s2 on stage 0)

        // ---- load B stage: WhT hi/lo bf16, 64 n-rows x 128 k, padded stride
        for (int idx = t; idx < 2048; idx += 256) {
            int half = idx >> 10;          // 0 = hi, 1 = lo
            int rem = idx & 1023;
            int n = rem >> 4;              // 0..63
            int seg = rem & 15;            // 16B segment
            const __nv_bfloat16* gsrc = (half ? g_WhT_lo : g_WhT_hi) + (size_t)n * NN + jStage;
            uint4 v = ((const uint4*)gsrc)[seg];
            *(uint4*)(Bs + half * BHALF + n * BSTRIDE + seg * 16) = v;
        }
        __syncthreads();

        // ---- 8 chunks of 16 j
#pragma unroll 2
        for (int c = 0; c < 8; ++c) {
            const int jc = stage * BK + c * 16 + 2 * qm;   // local j (within span)

            // consume prefetched adj, then prefetch next chunk
            int2 A0 = A0n, A1 = A1n, A2 = A2n, A3 = A3n;
            {
                int gjn = (c < 7) ? (jStage + (c + 1) * 16 + 2 * qm)
                                  : ((stage < JSPAN / BK - 1) ? (jStage + BK + 2 * qm)
                                                              : (jStart + 2 * qm));
                A0n = __ldg((const int2*)(row0 + gjn));
                A2n = __ldg((const int2*)(row0 + gjn + 8));
                A1n = __ldg((const int2*)(row1 + gjn));
                A3n = __ldg((const int2*)(row1 + gjn + 8));
            }

            float2 s2a = *(const float2*)&s2_s[jc];
            float2 s2b = *(const float2*)&s2_s[jc + 8];

            float e, p00, p01, p02, p03, p10, p11, p12, p13;
            e = s1r0 + s2a.x; e = fmaxf(e, ALPHA * e); p00 = (A0.x > 0) ? __expf(e) : 0.f;
            e = s1r0 + s2a.y; e = fmaxf(e, ALPHA * e); p01 = (A0.y > 0) ? __expf(e) : 0.f;
            e = s1r0 + s2b.x; e = fmaxf(e, ALPHA * e); p02 = (A2.x > 0) ? __expf(e) : 0.f;
            e = s1r0 + s2b.y; e = fmaxf(e, ALPHA * e); p03 = (A2.y > 0) ? __expf(e) : 0.f;
            e = s1r1 + s2a.x; e = fmaxf(e, ALPHA * e); p10 = (A1.x > 0) ? __expf(e) : 0.f;
            e = s1r1 + s2a.y; e = fmaxf(e, ALPHA * e); p11 = (A1.y > 0) ? __expf(e) : 0.f;
            e = s1r1 + s2b.x; e = fmaxf(e, ALPHA * e); p12 = (A3.x > 0) ? __expf(e) : 0.f;
            e = s1r1 + s2b.y; e = fmaxf(e, ALPHA * e); p13 = (A3.y > 0) ? __expf(e) : 0.f;

            lsum0 += (p00 + p01) + (p02 + p03);
            lsum1 += (p10 + p11) + (p12 + p13);

            // hi/lo fragment packing (truncation split)
            uint32_t a0h = pack_bf16(p00, p01), a2h = pack_bf16(p02, p03);
            uint32_t a1h = pack_bf16(p10, p11), a3h = pack_bf16(p12, p13);
            uint32_t a0l = pack_bf16(p00 - bf16_trunc_f(p00), p01 - bf16_trunc_f(p01));
            uint32_t a2l = pack_bf16(p02 - bf16_trunc_f(p02), p03 - bf16_trunc_f(p03));
            uint32_t a1l = pack_bf16(p10 - bf16_trunc_f(p10), p11 - bf16_trunc_f(p11));
            uint32_t a3l = pack_bf16(p12 - bf16_trunc_f(p12), p13 - bf16_trunc_f(p13));

            // base byte offset within a B n-row for this chunk + lane k
            const int kOff = c * 32 + qm * 4;
#pragma unroll
            for (int nt = 0; nt < 8; ++nt) {
                const unsigned char* bp = Bs + (nt * 8 + qr) * BSTRIDE + kOff;
                uint32_t bh0 = *(const uint32_t*)bp;
                uint32_t bh1 = *(const uint32_t*)(bp + 16);
                uint32_t bl0 = *(const uint32_t*)(bp + BHALF);
                uint32_t bl1 = *(const uint32_t*)(bp + BHALF + 16);
                mma16816(d[nt], a0h, a1h, a2h, a3h, bh0, bh1);
                mma16816(d[nt], a0h, a1h, a2h, a3h, bl0, bl1);
                mma16816(d[nt], a0l, a1l, a2l, a3l, bh0, bh1);
            }
        }
    }

    // ---- row sums: reduce across the 4 lanes of each quad-column group
    lsum0 += __shfl_xor_sync(0xffffffffu, lsum0, 1);
    lsum0 += __shfl_xor_sync(0xffffffffu, lsum0, 2);
    lsum1 += __shfl_xor_sync(0xffffffffu, lsum1, 1);
    lsum1 += __shfl_xor_sync(0xffffffffu, lsum1, 2);
    if (qm == 0) {
        g_lP[split][iBase + r0] = lsum0;
        g_lP[split][iBase + r1] = lsum1;
    }

    // ---- write partials: d[nt] = rows (r0, r1), cols nt*8 + 2*qm + {0,1}
    {
        float* base0 = &g_accP[split][iBase + r0][0];
        float* base1 = &g_accP[split][iBase + r1][0];
#pragma unroll
        for (int nt = 0; nt < 8; ++nt) {
            int cb = nt * 8 + 2 * qm;
            *(float2*)&base0[cb] = make_float2(d[nt][0], d[nt][1]);
            *(float2*)&base1[cb] = make_float2(d[nt][2], d[nt][3]);
        }
    }
}

// ---------------------------------------------------------------------------
// Kernel 3: sum split partials -> normalize -> ELU.
// ---------------------------------------------------------------------------
__global__ __launch_bounds__(256) void combine_kernel(float* __restrict__ out) {
    __shared__ float linv_s[16];
    const int t = threadIdx.x;
    const int rowBase = blockIdx.x * 16;

    if (t < 16) {
        int row = rowBase + t;
        float L = 0.f;
#pragma unroll
        for (int s = 0; s < SPLITS; ++s) L += g_lP[s][row];
        linv_s[t] = 1.f / L;
    }
    __syncthreads();

    const int rr = t >> 4;
    const int c4 = t & 15;
    const int row = rowBase + rr;

    float4 acc = make_float4(0.f, 0.f, 0.f, 0.f);
#pragma unroll
    for (int s = 0; s < SPLITS; ++s) {
        float4 v = *(const float4*)&g_accP[s][row][c4 * 4];
        acc.x += v.x; acc.y += v.y; acc.z += v.z; acc.w += v.w;
    }
    float li = linv_s[rr];
    float x0 = acc.x * li, x1 = acc.y * li, x2 = acc.z * li, x3 = acc.w * li;
    x0 = (x0 > 0.f) ? x0 : expm1f(x0);
    x1 = (x1 > 0.f) ? x1 : expm1f(x1);
    x2 = (x2 > 0.f) ? x2 : expm1f(x2);
    x3 = (x3 > 0.f) ? x3 : expm1f(x3);
    *(float4*)&out[(size_t)row * OUT_F + c4 * 4] = make_float4(x0, x1, x2, x3);
}

// ---------------------------------------------------------------------------
extern "C" void kernel_launch(void* const* d_in, const int* in_sizes, int n_in,
                              void* d_out, int out_size) {
    const float* h   = (const float*)d_in[0];   // 8192 x 128
    const int*   adj = (const int*)d_in[1];     // 8192 x 8192
    const float* W   = (const float*)d_in[2];   // 128 x 64
    const float* a   = (const float*)d_in[3];   // 128 x 1
    float* out = (float*)d_out;                 // 8192 x 64

    wh_kernel<<<NN / 16, 256>>>(h, W, a);
    attn_kernel<<<dim3(NTI, SPLITS), 256>>>(adj);
    combine_kernel<<<NN / 16, 256>>>(out);
}